// round 16
// baseline (speedup 1.0000x reference)
#include <cuda_runtime.h>
#include <cstdint>

// TT embedding lookup: bucket x column-half x pass decomposition.
//   P=(216,216,216), Q=(2,4,2), R=(128,128), tables=2, batch=1024
//   out[t,b, q0*8+q1*2+q2] = sum_{r0,r1} A[q0,r0]*Bm[r0, q1*128+r1]*C[r1,q2]
//
// Grid (432 buckets, 2 halves, 4 passes), block 64. Each CTA scans its
// table's 1024 indices (L2-hot) for samples with its i1 and takes samples
// [p*6, p*6+6). It owns one COLUMN HALF of the bucket's 256KB core1 slice
// (q1 pair {0,1} or {2,3} = bytes [h*1K, h*1K+1K) of each 2KB row), so it
// computes complete, disjoint outputs -> direct stores, no atomics.
// The half streams through a 4x8KB smem ring; each 8-row stage is 8
// separate 1KB cp.async.bulk copies onto one mbarrier (expect_tx=8KB).
// Thread t owns 4 cols (warp w = local q1); packed fma.rn.f32x2 accums,
// exact-KK dispatch. ~1060 working CTAs (~7/SM) to saturate DRAM.

#define P0 216
#define P1 216
#define P2 216
#define TABLES 2
#define SMAXU 6
#define NP 4                    // passes per bucket: covers k <= 24
#define ROWS_PER_STAGE 8
#define NBUF 4
#define NSTAGE_TOT 16           // 128 rows / 8
#define ROW_FLOATS 256          // half-row: 256 floats = 1KB
#define STAGE_BYTES (ROWS_PER_STAGE * ROW_FLOATS * 4)   // 8192
#define LISTCAP 40
#define NCONS 64

// ---- packed f32x2 helpers --------------------------------------------------
__device__ __forceinline__ void ffma2(unsigned long long& d,
                                      unsigned long long a,
                                      unsigned long long b) {
    asm("fma.rn.f32x2 %0, %1, %2, %0;" : "+l"(d) : "l"(a), "l"(b));
}
__device__ __forceinline__ unsigned long long splat2(float v) {
    unsigned long long r;
    unsigned int u = __float_as_uint(v);
    asm("mov.b64 %0, {%1, %1};" : "=l"(r) : "r"(u));
    return r;
}
__device__ __forceinline__ void unpack2(unsigned long long v, float& lo, float& hi) {
    unsigned int a, b;
    asm("mov.b64 {%0, %1}, %2;" : "=r"(a), "=r"(b) : "l"(v));
    lo = __uint_as_float(a);
    hi = __uint_as_float(b);
}

// ---- async-copy / mbarrier helpers ----------------------------------------
__device__ __forceinline__ uint32_t smem_u32(const void* p) {
    return (uint32_t)__cvta_generic_to_shared(p);
}
__device__ __forceinline__ void mbar_init(uint32_t mbar, uint32_t cnt) {
    asm volatile("mbarrier.init.shared.b64 [%0], %1;" :: "r"(mbar), "r"(cnt) : "memory");
}
__device__ __forceinline__ void mbar_expect_tx(uint32_t mbar, uint32_t bytes) {
    asm volatile("mbarrier.arrive.expect_tx.shared.b64 _, [%0], %1;"
                 :: "r"(mbar), "r"(bytes) : "memory");
}
__device__ __forceinline__ void bulk_ld(uint32_t dst, const void* src,
                                        uint32_t bytes, uint32_t mbar) {
    asm volatile("cp.async.bulk.shared::cta.global.mbarrier::complete_tx::bytes "
                 "[%0], [%1], %2, [%3];"
                 :: "r"(dst), "l"(src), "r"(bytes), "r"(mbar) : "memory");
}
__device__ __forceinline__ void mbar_wait(uint32_t mbar, uint32_t parity) {
    asm volatile(
        "{\n\t"
        ".reg .pred P;\n\t"
        "WL_%=:\n\t"
        "mbarrier.try_wait.parity.acquire.cta.shared::cta.b64 P, [%0], %1, 0x989680;\n\t"
        "@!P bra WL_%=;\n\t"
        "}"
        :: "r"(mbar), "r"(parity) : "memory");
}

// issue one 8-row stage as 8 x 1KB bulk copies onto one mbarrier
__device__ __forceinline__ void issue_stage(
    uint32_t sbuf0_u32, const float* __restrict__ half_base,
    int stage, int buf, uint32_t mb_u32)
{
    mbar_expect_tx(mb_u32 + 8 * buf, STAGE_BYTES);
    const float* src = half_base + (size_t)stage * ROWS_PER_STAGE * 512;
    uint32_t dst = sbuf0_u32 + buf * STAGE_BYTES;
    #pragma unroll
    for (int r = 0; r < ROWS_PER_STAGE; ++r)
        bulk_ld(dst + r * (ROW_FLOATS * 4), src + (size_t)r * 512,
                ROW_FLOATS * 4, mb_u32 + 8 * buf);
}

// ------------------------------------------------------- templated core ----
template <int KK>
__device__ __forceinline__ void run_unit(
    const float* __restrict__ half_base,          // slice + h*256
    const float* __restrict__ sbuf,
    uint32_t sbuf0_u32, uint32_t mb0_u32,
    const unsigned long long (*__restrict__ sA)[SMAXU],
    const int* __restrict__ sSid,
    const int* __restrict__ sI2,
    const float* __restrict__ core2_t,
    float* __restrict__ out,
    int t, int lane, int w, int half)
{
    unsigned long long acc[KK][4];
    #pragma unroll
    for (int j = 0; j < KK; ++j)
        #pragma unroll
        for (int c = 0; c < 4; ++c) acc[j][c] = 0ull;

    for (int s = 0; s < NSTAGE_TOT; ++s) {
        const int b = s & (NBUF - 1);
        mbar_wait(mb0_u32 + 8 * b, (s >> 2) & 1);

        const float* buf = sbuf + b * (ROWS_PER_STAGE * ROW_FLOATS) + 4 * t;
        const int rbase = s * ROWS_PER_STAGE;
        #pragma unroll
        for (int r = 0; r < ROWS_PER_STAGE; ++r) {
            const float4 v = *reinterpret_cast<const float4*>(buf + r * ROW_FLOATS);
            const unsigned long long vs0 = splat2(v.x);
            const unsigned long long vs1 = splat2(v.y);
            const unsigned long long vs2 = splat2(v.z);
            const unsigned long long vs3 = splat2(v.w);
            #pragma unroll
            for (int j = 0; j < KK; ++j) {
                const unsigned long long aj = sA[rbase + r][j];
                ffma2(acc[j][0], aj, vs0);
                ffma2(acc[j][1], aj, vs1);
                ffma2(acc[j][2], aj, vs2);
                ffma2(acc[j][3], aj, vs3);
            }
        }
        __syncthreads();   // buffer b fully consumed
        if (s + 3 < NSTAGE_TOT && t == 0)
            issue_stage(sbuf0_u32, half_base, s + 3, (s + 3) & (NBUF - 1), mb0_u32);
    }

    // epilogue: contract with C over thread's 4 r1 (= 4*lane..+3), reduce, store
    #pragma unroll
    for (int j = 0; j < KK; ++j) {
        const float* c = core2_t + (size_t)sI2[j] * 256;
        const float4 cA = *reinterpret_cast<const float4*>(c + 8 * lane);
        const float4 cB = *reinterpret_cast<const float4*>(c + 8 * lane + 4);
        float s00, s10, s01, s11, s02, s12, s03, s13;
        unpack2(acc[j][0], s00, s10);
        unpack2(acc[j][1], s01, s11);
        unpack2(acc[j][2], s02, s12);
        unpack2(acc[j][3], s03, s13);
        float o00 = s00 * cA.x + s01 * cA.z + s02 * cB.x + s03 * cB.z;
        float o01 = s00 * cA.y + s01 * cA.w + s02 * cB.y + s03 * cB.w;
        float o10 = s10 * cA.x + s11 * cA.z + s12 * cB.x + s13 * cB.z;
        float o11 = s10 * cA.y + s11 * cA.w + s12 * cB.y + s13 * cB.w;
        #pragma unroll
        for (int off = 16; off; off >>= 1) {
            o00 += __shfl_down_sync(0xffffffffu, o00, off);
            o01 += __shfl_down_sync(0xffffffffu, o01, off);
            o10 += __shfl_down_sync(0xffffffffu, o10, off);
            o11 += __shfl_down_sync(0xffffffffu, o11, off);
        }
        if (lane == 0) {
            const int q1 = 2 * half + w;
            float* op = out + (size_t)sSid[j] * 16;
            op[q1 * 2 + 0]     = o00;   // q0=0
            op[q1 * 2 + 1]     = o01;
            op[8 + q1 * 2 + 0] = o10;   // q0=1
            op[8 + q1 * 2 + 1] = o11;
        }
    }
}

// --------------------------------------------------------------- kernel ----
__global__ __launch_bounds__(NCONS) void tt_kernel(
    const int* __restrict__ lS_i,         // [T*B] int32
    const float* __restrict__ core0,      // [T, P0, 256]
    const float* __restrict__ core1,      // [T, P1, 65536]
    const float* __restrict__ core2,      // [T, P2, 256]
    float* __restrict__ out,              // [T*B, 16]
    int batch)
{
    const int bucket = blockIdx.x;        // 0..431
    const int table  = bucket / P1;
    const int i1t    = bucket % P1;
    const int half   = blockIdx.y;        // column half: q1 pair {0,1} or {2,3}
    const int p      = blockIdx.z;        // pass 0..NP-1

    const int t    = threadIdx.x;         // 0..63
    const int lane = t & 31;
    const int w    = t >> 5;              // 0/1 = local q1

    __shared__ __align__(16) float sbuf[NBUF * ROWS_PER_STAGE * ROW_FLOATS]; // 32KB
    __shared__ __align__(16) unsigned long long sA[128][SMAXU];              // 6KB
    __shared__ __align__(8) unsigned long long sMbar[NBUF];
    __shared__ int sList[LISTCAP];
    __shared__ int sWarpTot[2];
    __shared__ int sSid[SMAXU], sI2[SMAXU];

    const uint32_t mb0_u32   = smem_u32(&sMbar[0]);
    const uint32_t sbuf0_u32 = smem_u32(sbuf);

    if (t == 0) {
        #pragma unroll
        for (int b = 0; b < NBUF; ++b) mbar_init(mb0_u32 + 8 * b, 1);
    }

    // ---- scan this table's indices for i1 == i1t (two-pass, canonical) ----
    const int per = batch >> 6;           // 16 for batch=1024
    const int s0  = table * batch + t * per;
    const int4* ip = reinterpret_cast<const int4*>(lS_i + s0);
    int cnt = 0;
    #pragma unroll
    for (int q = 0; q < 4; ++q) {
        const int4 u = ip[q];
        cnt += ((u.x / P2) % P1 == i1t);
        cnt += ((u.y / P2) % P1 == i1t);
        cnt += ((u.z / P2) % P1 == i1t);
        cnt += ((u.w / P2) % P1 == i1t);
    }
    int inc = cnt;
    #pragma unroll
    for (int off = 1; off < 32; off <<= 1) {
        const int v = __shfl_up_sync(0xffffffffu, inc, off);
        if (lane >= off) inc += v;
    }
    if (lane == 31) sWarpTot[w] = inc;
    __syncthreads();
    const int ktot = sWarpTot[0] + sWarpTot[1];
    int pos = (w ? sWarpTot[0] : 0) + inc - cnt;
    #pragma unroll
    for (int q = 0; q < 4; ++q) {
        const int4 u = ip[q];
        const int v[4] = {u.x, u.y, u.z, u.w};
        #pragma unroll
        for (int j = 0; j < 4; ++j) {
            if ((v[j] / P2) % P1 == i1t) {
                if (pos < LISTCAP) sList[pos] = s0 + q * 4 + j;
                ++pos;
            }
        }
    }
    __syncthreads();

    const int kk = min(SMAXU, ktot - p * SMAXU);
    if (kk <= 0) return;

    const float* half_base = core1 + ((size_t)bucket) * 65536 + half * 256;

    // prologue: issue 3 stages (overlaps with sA setup)
    if (t == 0) {
        #pragma unroll
        for (int s = 0; s < 3; ++s)
            issue_stage(sbuf0_u32, half_base, s, s, mb0_u32);
    }

    if (t < kk) {
        const int sid = sList[p * SMAXU + t];
        sSid[t] = sid;
        sI2[t]  = lS_i[sid] % P2;
    }

    // A slices: thread t covers rows t and t+64, all kk samples
    #pragma unroll
    for (int rep = 0; rep < 2; ++rep) {
        const int r = t + rep * 64;
        #pragma unroll
        for (int j = 0; j < SMAXU; ++j) {
            unsigned long long pack = 0ull;
            if (j < kk) {
                const int sid = sList[p * SMAXU + j];
                const int id  = lS_i[sid];
                const int i0  = id / (P1 * P2);
                const float* a = core0 + ((size_t)(table * P0 + i0)) * 256;
                const unsigned int a0 = __float_as_uint(a[r]);
                const unsigned int a1 = __float_as_uint(a[r + 128]);
                pack = (unsigned long long)a0 | ((unsigned long long)a1 << 32);
            }
            sA[r][j] = pack;
        }
    }
    __syncthreads();   // sA + metadata + mbar init visible

    const float* core2_t = core2 + (size_t)table * P2 * 256;

    switch (kk) {
        case 6: run_unit<6>(half_base, sbuf, sbuf0_u32, mb0_u32, sA, sSid, sI2, core2_t, out, t, lane, w, half); break;
        case 5: run_unit<5>(half_base, sbuf, sbuf0_u32, mb0_u32, sA, sSid, sI2, core2_t, out, t, lane, w, half); break;
        case 4: run_unit<4>(half_base, sbuf, sbuf0_u32, mb0_u32, sA, sSid, sI2, core2_t, out, t, lane, w, half); break;
        case 3: run_unit<3>(half_base, sbuf, sbuf0_u32, mb0_u32, sA, sSid, sI2, core2_t, out, t, lane, w, half); break;
        case 2: run_unit<2>(half_base, sbuf, sbuf0_u32, mb0_u32, sA, sSid, sI2, core2_t, out, t, lane, w, half); break;
        default: run_unit<1>(half_base, sbuf, sbuf0_u32, mb0_u32, sA, sSid, sI2, core2_t, out, t, lane, w, half); break;
    }
}

// --------------------------------------------------------------- launch ----
extern "C" void kernel_launch(void* const* d_in, const int* in_sizes, int n_in,
                              void* d_out, int out_size) {
    const int*   lS_i  = (const int*)d_in[0];
    const float* core0 = (const float*)d_in[1];
    const float* core1 = (const float*)d_in[2];
    const float* core2 = (const float*)d_in[3];
    float*       out   = (float*)d_out;

    const int n_samples = in_sizes[0];        // TABLES * batch = 2048
    const int batch     = n_samples / TABLES;

    dim3 grid(TABLES * P1, 2, NP);
    tt_kernel<<<grid, NCONS>>>(lS_i, core0, core1, core2, out, batch);
}

// round 17
// speedup vs baseline: 1.3504x; 1.3504x over previous
#include <cuda_runtime.h>
#include <cstdint>

// TT embedding lookup: single-kernel dedup, 8-warp CTAs, bulk-async ring.
//   P=(216,216,216), Q=(2,4,2), R=(128,128), tables=2, batch=1024
//   out[t,b, q0*8+q1*2+q2] = sum_{r0,r1} A[q0,r0]*Bm[r0, q1*128+r1]*C[r1,q2]
//
// Grid (432 buckets, 4 passes), block 256 (8 warps). Each CTA scans its
// table's 1024 indices (L2-hot) for samples with its i1, takes samples
// [p*6, p*6+6). The bucket's contiguous 256KB core1 slice streams through
// a 3x16KB smem ring via cp.async.bulk + mbarrier expect_tx (2 in flight).
// Thread t owns cols 2t..2t+1 (q1 = t>>6, two warps per q1); packed
// fma.rn.f32x2 accumulators; exact-KK dispatch; partials combined via smem.

#define P0 216
#define P1 216
#define P2 216
#define TABLES 2
#define SMAXU 6
#define NP 4                     // passes per bucket: covers k <= 24
#define ROWS_PER_STAGE 8
#define NBUF 3
#define NSTAGE_TOT 16            // 128 rows / 8
#define STAGE_BYTES (ROWS_PER_STAGE * 512 * 4)   // 16384
#define LISTCAP 40
#define NT 256

// ---- packed f32x2 helpers --------------------------------------------------
__device__ __forceinline__ void ffma2(unsigned long long& d,
                                      unsigned long long a,
                                      unsigned long long b) {
    asm("fma.rn.f32x2 %0, %1, %2, %0;" : "+l"(d) : "l"(a), "l"(b));
}
__device__ __forceinline__ unsigned long long splat2(float v) {
    unsigned long long r;
    unsigned int u = __float_as_uint(v);
    asm("mov.b64 %0, {%1, %1};" : "=l"(r) : "r"(u));
    return r;
}
__device__ __forceinline__ void unpack2(unsigned long long v, float& lo, float& hi) {
    unsigned int a, b;
    asm("mov.b64 {%0, %1}, %2;" : "=r"(a), "=r"(b) : "l"(v));
    lo = __uint_as_float(a);
    hi = __uint_as_float(b);
}

// ---- async-copy / mbarrier helpers ----------------------------------------
__device__ __forceinline__ uint32_t smem_u32(const void* p) {
    return (uint32_t)__cvta_generic_to_shared(p);
}
__device__ __forceinline__ void mbar_init(uint32_t mbar, uint32_t cnt) {
    asm volatile("mbarrier.init.shared.b64 [%0], %1;" :: "r"(mbar), "r"(cnt) : "memory");
}
__device__ __forceinline__ void mbar_expect_tx(uint32_t mbar, uint32_t bytes) {
    asm volatile("mbarrier.arrive.expect_tx.shared.b64 _, [%0], %1;"
                 :: "r"(mbar), "r"(bytes) : "memory");
}
__device__ __forceinline__ void bulk_ld(uint32_t dst, const void* src,
                                        uint32_t bytes, uint32_t mbar) {
    asm volatile("cp.async.bulk.shared::cta.global.mbarrier::complete_tx::bytes "
                 "[%0], [%1], %2, [%3];"
                 :: "r"(dst), "l"(src), "r"(bytes), "r"(mbar) : "memory");
}
__device__ __forceinline__ void mbar_wait(uint32_t mbar, uint32_t parity) {
    asm volatile(
        "{\n\t"
        ".reg .pred P;\n\t"
        "WL_%=:\n\t"
        "mbarrier.try_wait.parity.acquire.cta.shared::cta.b64 P, [%0], %1, 0x989680;\n\t"
        "@!P bra WL_%=;\n\t"
        "}"
        :: "r"(mbar), "r"(parity) : "memory");
}

// ------------------------------------------------------- templated core ----
template <int KK>
__device__ __forceinline__ void run_unit(
    const float* __restrict__ slice,
    const float* __restrict__ sbuf,
    uint32_t sbuf0_u32, uint32_t mb0_u32,
    const unsigned long long (*__restrict__ sA)[SMAXU],
    const int* __restrict__ sSid,
    const int* __restrict__ sI2,
    const float* __restrict__ core2_t,
    float (*__restrict__ sP)[8][4],
    float* __restrict__ out,
    int t, int lane, int w)
{
    // acc[j][c]: c = thread's column (0/1), packs (q0=0, q0=1)
    unsigned long long acc[KK][2];
    #pragma unroll
    for (int j = 0; j < KK; ++j) { acc[j][0] = 0ull; acc[j][1] = 0ull; }

    int use_b = 0, use_ph = 0;       // consumer ring cursor
    for (int s = 0; s < NSTAGE_TOT; ++s) {
        mbar_wait(mb0_u32 + 8 * use_b, use_ph);

        const float* buf = sbuf + use_b * (ROWS_PER_STAGE * 512) + 2 * t;
        const int rbase = s * ROWS_PER_STAGE;
        #pragma unroll
        for (int r = 0; r < ROWS_PER_STAGE; ++r) {
            const float2 v = *reinterpret_cast<const float2*>(buf + r * 512);
            const unsigned long long vs0 = splat2(v.x);
            const unsigned long long vs1 = splat2(v.y);
            #pragma unroll
            for (int j = 0; j < KK; ++j) {
                const unsigned long long aj = sA[rbase + r][j];
                ffma2(acc[j][0], aj, vs0);
                ffma2(acc[j][1], aj, vs1);
            }
        }
        __syncthreads();   // buffer fully consumed
        if (s + 2 < NSTAGE_TOT && t == 0) {
            const int ns = s + 2;
            int nb = use_b + 2; if (nb >= NBUF) nb -= NBUF;
            mbar_expect_tx(mb0_u32 + 8 * nb, STAGE_BYTES);
            bulk_ld(sbuf0_u32 + nb * STAGE_BYTES,
                    slice + (size_t)ns * ROWS_PER_STAGE * 512,
                    STAGE_BYTES, mb0_u32 + 8 * nb);
        }
        if (++use_b == NBUF) { use_b = 0; use_ph ^= 1; }
    }

    // epilogue: thread covers r1a=2t&127 and r1a+1; two warps share each q1.
    const int r1a = (2 * t) & 127;
    #pragma unroll
    for (int j = 0; j < KK; ++j) {
        const float* c = core2_t + (size_t)sI2[j] * 256;
        const float4 cv = *reinterpret_cast<const float4*>(c + 2 * r1a);
        float s0a, s1a, s0b, s1b;
        unpack2(acc[j][0], s0a, s1a);    // S[q0][col0]
        unpack2(acc[j][1], s0b, s1b);    // S[q0][col1]
        float o00 = s0a * cv.x + s0b * cv.z;
        float o01 = s0a * cv.y + s0b * cv.w;
        float o10 = s1a * cv.x + s1b * cv.z;
        float o11 = s1a * cv.y + s1b * cv.w;
        #pragma unroll
        for (int off = 16; off; off >>= 1) {
            o00 += __shfl_down_sync(0xffffffffu, o00, off);
            o01 += __shfl_down_sync(0xffffffffu, o01, off);
            o10 += __shfl_down_sync(0xffffffffu, o10, off);
            o11 += __shfl_down_sync(0xffffffffu, o11, off);
        }
        if (lane == 0) {
            sP[j][w][0] = o00;   // q0=0,q2=0
            sP[j][w][1] = o01;   // q0=0,q2=1
            sP[j][w][2] = o10;   // q0=1,q2=0
            sP[j][w][3] = o11;   // q0=1,q2=1
        }
    }
    __syncthreads();

    // combine warp pairs: warp 2q1 (r1 0..63) + warp 2q1+1 (r1 64..127)
    if (t < KK * 16) {
        const int j  = t >> 4;
        const int q1 = (t >> 2) & 3;
        const int v  = t & 3;            // q0 = v>>1, q2 = v&1
        const float o = sP[j][2 * q1][v] + sP[j][2 * q1 + 1][v];
        out[(size_t)sSid[j] * 16 + (v >> 1) * 8 + q1 * 2 + (v & 1)] = o;
    }
}

// --------------------------------------------------------------- kernel ----
__global__ __launch_bounds__(NT) void tt_kernel(
    const int* __restrict__ lS_i,         // [T*B] int32
    const float* __restrict__ core0,      // [T, P0, 256]
    const float* __restrict__ core1,      // [T, P1, 65536]
    const float* __restrict__ core2,      // [T, P2, 256]
    float* __restrict__ out,              // [T*B, 16]
    int batch)
{
    const int bucket = blockIdx.x;        // 0..431
    const int table  = bucket / P1;
    const int i1t    = bucket % P1;
    const int p      = blockIdx.y;        // pass 0..NP-1

    const int t    = threadIdx.x;         // 0..255
    const int lane = t & 31;
    const int w    = t >> 5;              // warp 0..7; q1 = w>>1

    __shared__ __align__(16) float sbuf[NBUF * ROWS_PER_STAGE * 512];  // 48KB
    __shared__ __align__(16) unsigned long long sA[128][SMAXU];        // 6KB
    __shared__ __align__(8) unsigned long long sMbar[NBUF];
    __shared__ float sP[SMAXU][8][4];
    __shared__ int sList[LISTCAP];
    __shared__ int sWarpTot[8];
    __shared__ int sSid[SMAXU], sI2[SMAXU];

    const uint32_t mb0_u32   = smem_u32(&sMbar[0]);
    const uint32_t sbuf0_u32 = smem_u32(sbuf);

    if (t == 0) {
        #pragma unroll
        for (int b = 0; b < NBUF; ++b) mbar_init(mb0_u32 + 8 * b, 1);
    }

    // ---- scan this table's indices for i1 == i1t (canonical order) ----
    const int per = batch >> 8;           // 4 for batch=1024
    const int s0  = table * batch + t * per;
    const int4 u  = *reinterpret_cast<const int4*>(lS_i + s0);
    const int vv[4] = {u.x, u.y, u.z, u.w};
    int cnt = 0;
    #pragma unroll
    for (int j = 0; j < 4; ++j) cnt += ((vv[j] / P2) % P1 == i1t);

    int inc = cnt;
    #pragma unroll
    for (int off = 1; off < 32; off <<= 1) {
        const int x = __shfl_up_sync(0xffffffffu, inc, off);
        if (lane >= off) inc += x;
    }
    if (lane == 31) sWarpTot[w] = inc;
    __syncthreads();
    int warpBase = 0;
    #pragma unroll
    for (int ww = 0; ww < 8; ++ww)
        if (ww < w) warpBase += sWarpTot[ww];
    int ktot = 0;
    #pragma unroll
    for (int ww = 0; ww < 8; ++ww) ktot += sWarpTot[ww];
    int pos = warpBase + inc - cnt;
    #pragma unroll
    for (int j = 0; j < 4; ++j) {
        if ((vv[j] / P2) % P1 == i1t) {
            if (pos < LISTCAP) sList[pos] = s0 + j;
            ++pos;
        }
    }
    __syncthreads();

    const int kk = min(SMAXU, ktot - p * SMAXU);
    if (kk <= 0) return;

    const float* slice = core1 + ((size_t)bucket) * 65536;

    // prologue: issue stages 0,1 (overlaps with sA setup)
    if (t == 0) {
        #pragma unroll
        for (int s = 0; s < 2; ++s) {
            mbar_expect_tx(mb0_u32 + 8 * s, STAGE_BYTES);
            bulk_ld(sbuf0_u32 + s * STAGE_BYTES,
                    slice + (size_t)s * ROWS_PER_STAGE * 512,
                    STAGE_BYTES, mb0_u32 + 8 * s);
        }
    }

    if (t < kk) {
        const int sid = sList[p * SMAXU + t];
        sSid[t] = sid;
        sI2[t]  = lS_i[sid] % P2;
    }

    // A slices: thread t covers row r = t&127, j-range half = t>>7
    {
        const int r  = t & 127;
        const int jh = (t >> 7) * 3;           // 0 or 3
        #pragma unroll
        for (int jj = 0; jj < 3; ++jj) {
            const int j = jh + jj;
            unsigned long long pack = 0ull;
            if (j < kk) {
                const int sid = sList[p * SMAXU + j];
                const int id  = lS_i[sid];
                const int i0  = id / (P1 * P2);
                const float* a = core0 + ((size_t)(table * P0 + i0)) * 256;
                const unsigned int a0 = __float_as_uint(a[r]);
                const unsigned int a1 = __float_as_uint(a[r + 128]);
                pack = (unsigned long long)a0 | ((unsigned long long)a1 << 32);
            }
            if (j < SMAXU) sA[r][j] = pack;
        }
    }
    __syncthreads();   // sA + metadata + mbar init visible

    const float* core2_t = core2 + (size_t)table * P2 * 256;

    switch (kk) {
        case 6: run_unit<6>(slice, sbuf, sbuf0_u32, mb0_u32, sA, sSid, sI2, core2_t, sP, out, t, lane, w); break;
        case 5: run_unit<5>(slice, sbuf, sbuf0_u32, mb0_u32, sA, sSid, sI2, core2_t, sP, out, t, lane, w); break;
        case 4: run_unit<4>(slice, sbuf, sbuf0_u32, mb0_u32, sA, sSid, sI2, core2_t, sP, out, t, lane, w); break;
        case 3: run_unit<3>(slice, sbuf, sbuf0_u32, mb0_u32, sA, sSid, sI2, core2_t, sP, out, t, lane, w); break;
        case 2: run_unit<2>(slice, sbuf, sbuf0_u32, mb0_u32, sA, sSid, sI2, core2_t, sP, out, t, lane, w); break;
        default: run_unit<1>(slice, sbuf, sbuf0_u32, mb0_u32, sA, sSid, sI2, core2_t, sP, out, t, lane, w); break;
    }
}

// --------------------------------------------------------------- launch ----
extern "C" void kernel_launch(void* const* d_in, const int* in_sizes, int n_in,
                              void* d_out, int out_size) {
    const int*   lS_i  = (const int*)d_in[0];
    const float* core0 = (const float*)d_in[1];
    const float* core1 = (const float*)d_in[2];
    const float* core2 = (const float*)d_in[3];
    float*       out   = (float*)d_out;

    const int n_samples = in_sizes[0];        // TABLES * batch = 2048
    const int batch     = n_samples / TABLES;

    dim3 grid(TABLES * P1, NP);
    tt_kernel<<<grid, NT>>>(lS_i, core0, core1, core2, out, batch);
}